// round 1
// baseline (speedup 1.0000x reference)
#include <cuda_runtime.h>

// Problem constants (fixed shapes from reference setup_inputs)
#define BB 128      // batch
#define SS 513      // sequence
#define HH 256      // hidden
#define BM 64       // batch-tile
#define BN 64       // out-dim tile
#define BK 32       // k tile

// out[b,s,d] = sum_h x[b,s,h] * W[idx(s), d, h] + sum_l bias[l,d]
// idx(s) = s for s<3, else (s odd ? 3 : 4)
__global__ __launch_bounds__(256, 2)
void pmha_gemm_kernel(const float* __restrict__ x,
                      const float* __restrict__ W,
                      const float* __restrict__ bias,
                      float* __restrict__ out)
{
    __shared__ float Xs[BK][BM];   // Xs[k][m]  (transposed)
    __shared__ float Ws[BK][BN];   // Ws[k][n]  (transposed)
    __shared__ float bsum[BN];

    const int s   = blockIdx.z;
    const int n0  = blockIdx.x * BN;
    const int m0  = blockIdx.y * BM;
    const int tid = threadIdx.x;

    const int widx = (s < 3) ? s : ((s & 1) ? 3 : 4);
    const float* __restrict__ Wp = W + (size_t)widx * HH * HH;

    // Pre-sum the 5 bias vectors for this n-tile
    if (tid < BN) {
        float v = 0.0f;
        #pragma unroll
        for (int l = 0; l < 5; ++l) v += bias[l * HH + n0 + tid];
        bsum[tid] = v;
    }

    const int tx = tid & 15;   // n direction (16)
    const int ty = tid >> 4;   // m direction (16)

    float acc[4][4] = {};

    const float* __restrict__ xbase = x + (size_t)s * HH;

    for (int k0 = 0; k0 < HH; k0 += BK) {
        // ---- load X tile: 64 rows (batch) x 32 k, float4 along k, store transposed
        #pragma unroll
        for (int j = 0; j < 2; ++j) {
            int vid = tid + j * 256;         // 512 float4s total
            int row = vid >> 3;              // 0..63
            int kc  = vid & 7;               // 0..7 (float4 column)
            float4 v = *(const float4*)(xbase + (size_t)(m0 + row) * (SS * HH) + k0 + kc * 4);
            Xs[kc * 4 + 0][row] = v.x;
            Xs[kc * 4 + 1][row] = v.y;
            Xs[kc * 4 + 2][row] = v.z;
            Xs[kc * 4 + 3][row] = v.w;
        }
        // ---- load W tile: 64 rows (out-dim d) x 32 k (W[d,h] rows contiguous in h)
        #pragma unroll
        for (int j = 0; j < 2; ++j) {
            int vid = tid + j * 256;
            int row = vid >> 3;
            int kc  = vid & 7;
            float4 v = *(const float4*)(Wp + (size_t)(n0 + row) * HH + k0 + kc * 4);
            Ws[kc * 4 + 0][row] = v.x;
            Ws[kc * 4 + 1][row] = v.y;
            Ws[kc * 4 + 2][row] = v.z;
            Ws[kc * 4 + 3][row] = v.w;
        }
        __syncthreads();

        // ---- mainloop: 4x4 micro-tile per thread
        #pragma unroll
        for (int k = 0; k < BK; ++k) {
            float4 xa = *(const float4*)&Xs[k][ty * 4];
            float4 wb = *(const float4*)&Ws[k][tx * 4];
            float xv[4] = {xa.x, xa.y, xa.z, xa.w};
            float wv[4] = {wb.x, wb.y, wb.z, wb.w};
            #pragma unroll
            for (int i = 0; i < 4; ++i)
                #pragma unroll
                for (int jj = 0; jj < 4; ++jj)
                    acc[i][jj] += xv[i] * wv[jj];
        }
        __syncthreads();
    }

    // ---- epilogue: add bias sums, float4 stores (n contiguous)
    const float bx = bsum[tx * 4 + 0];
    const float by = bsum[tx * 4 + 1];
    const float bz = bsum[tx * 4 + 2];
    const float bw = bsum[tx * 4 + 3];
    #pragma unroll
    for (int i = 0; i < 4; ++i) {
        int m = m0 + ty * 4 + i;
        float4 o;
        o.x = acc[i][0] + bx;
        o.y = acc[i][1] + by;
        o.z = acc[i][2] + bz;
        o.w = acc[i][3] + bw;
        *(float4*)(out + (size_t)m * (SS * HH) + (size_t)s * HH + n0 + tx * 4) = o;
    }
}

extern "C" void kernel_launch(void* const* d_in, const int* in_sizes, int n_in,
                              void* d_out, int out_size)
{
    const float* x    = (const float*)d_in[0];   // [128, 513, 256]
    const float* W    = (const float*)d_in[1];   // [5, 256, 256]
    const float* bias = (const float*)d_in[2];   // [5, 256]
    float* out        = (float*)d_out;           // [128, 513, 4, 64] == [128,513,256]

    dim3 grid(HH / BN, BB / BM, SS);   // (4, 2, 513)
    dim3 block(256);
    pmha_gemm_kernel<<<grid, block>>>(x, W, bias, out);
}

// round 3
// speedup vs baseline: 3.2859x; 3.2859x over previous
#include <cuda_runtime.h>
#include <cuda_bf16.h>
#include <cstdint>

#define SSEQ 513
#define HH   256
#define SSH  (SSEQ * HH)
#define KT   64            // k elements per smem tile
#define KPADB 144          // bytes per smem row: 64 bf16 = 128B + 16B pad (conflict-free ldmatrix)

// dynamic smem byte offsets
#define OXH 0
#define OXL (128 * KPADB)
#define OWH (2 * 128 * KPADB)
#define OWL (3 * 128 * KPADB)
#define OBS (4 * 128 * KPADB)          // 128 floats bias sums (this n-half)
#define SMTOT (OBS + 128 * 4)          // 74240 B

__device__ __forceinline__ uint32_t smem_u32(const void* p) {
    uint32_t a;
    asm("{ .reg .u64 t; cvta.to.shared.u64 t, %1; cvt.u32.u64 %0, t; }" : "=r"(a) : "l"(p));
    return a;
}

__device__ __forceinline__ void ldsm_x4(uint32_t* r, uint32_t addr) {
    asm volatile("ldmatrix.sync.aligned.m8n8.x4.shared.b16 {%0,%1,%2,%3}, [%4];"
                 : "=r"(r[0]), "=r"(r[1]), "=r"(r[2]), "=r"(r[3]) : "r"(addr));
}

__device__ __forceinline__ void mma_bf16(float* d, const uint32_t* a, uint32_t b0, uint32_t b1) {
    asm volatile(
        "mma.sync.aligned.m16n8k16.row.col.f32.bf16.bf16.f32 "
        "{%0,%1,%2,%3}, {%4,%5,%6,%7}, {%8,%9}, {%0,%1,%2,%3};"
        : "+f"(d[0]), "+f"(d[1]), "+f"(d[2]), "+f"(d[3])
        : "r"(a[0]), "r"(a[1]), "r"(a[2]), "r"(a[3]), "r"(b0), "r"(b1));
}

// split fp32 float4 -> bf16 hi + bf16 lo, 8B each into padded row-major tiles
__device__ __forceinline__ void cvt8(char* hb, char* lb, int row, int c4, float4 v) {
    __nv_bfloat16 h0 = __float2bfloat16(v.x);
    __nv_bfloat16 h1 = __float2bfloat16(v.y);
    __nv_bfloat16 h2 = __float2bfloat16(v.z);
    __nv_bfloat16 h3 = __float2bfloat16(v.w);
    __nv_bfloat16 l0 = __float2bfloat16(v.x - __bfloat162float(h0));
    __nv_bfloat16 l1 = __float2bfloat16(v.y - __bfloat162float(h1));
    __nv_bfloat16 l2 = __float2bfloat16(v.z - __bfloat162float(h2));
    __nv_bfloat16 l3 = __float2bfloat16(v.w - __bfloat162float(h3));
    uint32_t off = (uint32_t)row * KPADB + (uint32_t)c4 * 8u;
    __nv_bfloat162* hp = reinterpret_cast<__nv_bfloat162*>(hb + off);
    hp[0] = __halves2bfloat162(h0, h1);
    hp[1] = __halves2bfloat162(h2, h3);
    __nv_bfloat162* lp = reinterpret_cast<__nv_bfloat162*>(lb + off);
    lp[0] = __halves2bfloat162(l0, l1);
    lp[1] = __halves2bfloat162(l2, l3);
}

// CTA: sequence position s (blockIdx.y), n-half (blockIdx.x).
// out[0:128, s, n0:n0+128] = x[:, s, :] @ W[idx(s)]^T + bias_sum
__global__ __launch_bounds__(256, 2)
void pmha_mma_kernel(const float* __restrict__ x,
                     const float* __restrict__ W,
                     const float* __restrict__ bias,
                     float* __restrict__ out)
{
    extern __shared__ char smem[];
    const uint32_t sb = smem_u32(smem);
    const int tid  = threadIdx.x;
    const int lane = tid & 31;
    const int wid  = tid >> 5;
    const int s    = blockIdx.y;
    const int n0   = blockIdx.x * 128;
    const int widx = (s < 3) ? s : ((s & 1) ? 3 : 4);
    const int wm   = wid >> 2;    // 0..1 : warp row (64 m each)
    const int wn   = wid & 3;     // 0..3 : warp col (32 n each)

    float* bs = reinterpret_cast<float*>(smem + OBS);
    if (tid < 128) {
        float v = 0.0f;
        #pragma unroll
        for (int l = 0; l < 5; ++l) v += bias[l * HH + n0 + tid];
        bs[tid] = v;
    }

    const float* xs = x + (size_t)s * HH;
    const float* Wp = W + (size_t)widx * HH * HH + (size_t)n0 * HH;

    float acc[4][4][4] = {};   // [mtile16][ntile8][frag]

    // ldmatrix base addresses (row part); +32B per k16 step
    const int lr = lane & 15;
    const int lc = lane >> 4;
    uint32_t aAH[4], aAL[4], aBH[2], aBL[2];
    #pragma unroll
    for (int i = 0; i < 4; ++i) {
        int row = wm * 64 + i * 16 + lr;
        aAH[i] = sb + OXH + row * KPADB + lc * 16;
        aAL[i] = sb + OXL + row * KPADB + lc * 16;
    }
    #pragma unroll
    for (int jj = 0; jj < 2; ++jj) {
        int row = wn * 32 + jj * 16 + lr;
        aBH[jj] = sb + OWH + row * KPADB + lc * 16;
        aBL[jj] = sb + OWL + row * KPADB + lc * 16;
    }

    for (int kt = 0; kt < 4; ++kt) {
        const int k0 = kt * KT;
        __syncthreads();   // previous tile's compute done before overwrite

        // stage X tile (128 batch rows x 64 k) as bf16 hi/lo
        #pragma unroll
        for (int i = 0; i < 8; ++i) {
            int vid = tid + i * 256;
            int r = vid >> 4, c4 = vid & 15;
            float4 v = *reinterpret_cast<const float4*>(xs + (size_t)r * SSH + k0 + c4 * 4);
            cvt8(smem + OXH, smem + OXL, r, c4, v);
        }
        // stage W tile (128 n rows x 64 k) as bf16 hi/lo
        #pragma unroll
        for (int i = 0; i < 8; ++i) {
            int vid = tid + i * 256;
            int r = vid >> 4, c4 = vid & 15;
            float4 v = *reinterpret_cast<const float4*>(Wp + (size_t)r * HH + k0 + c4 * 4);
            cvt8(smem + OWH, smem + OWL, r, c4, v);
        }
        __syncthreads();

        #pragma unroll
        for (int ks = 0; ks < 4; ++ks) {
            const uint32_t koff = ks * 32;   // 16 bf16 = 32B per k-step
            uint32_t ah[4][4], al[4][4], bh[2][4], bl[2][4];
            #pragma unroll
            for (int i = 0; i < 4; ++i) {
                ldsm_x4(ah[i], aAH[i] + koff);
                ldsm_x4(al[i], aAL[i] + koff);
            }
            #pragma unroll
            for (int jj = 0; jj < 2; ++jj) {
                ldsm_x4(bh[jj], aBH[jj] + koff);
                ldsm_x4(bl[jj], aBL[jj] + koff);
            }
            #pragma unroll
            for (int i = 0; i < 4; ++i) {
                #pragma unroll
                for (int j = 0; j < 4; ++j) {
                    const int jj = j >> 1, sel = j & 1;
                    mma_bf16(acc[i][j], ah[i], bh[jj][sel], bh[jj][sel + 2]); // hh
                    mma_bf16(acc[i][j], ah[i], bl[jj][sel], bl[jj][sel + 2]); // hl
                    mma_bf16(acc[i][j], al[i], bh[jj][sel], bh[jj][sel + 2]); // lh
                }
            }
        }
    }

    // epilogue: d frag -> out, + bias
    const int tg  = lane >> 2;
    const int tig = lane & 3;
    #pragma unroll
    for (int i = 0; i < 4; ++i) {
        #pragma unroll
        for (int j = 0; j < 4; ++j) {
            const int c  = wn * 32 + j * 8 + tig * 2;
            const int m0r = wm * 64 + i * 16 + tg;
            const float b0 = bs[c], b1 = bs[c + 1];
            float2 v0 = make_float2(acc[i][j][0] + b0, acc[i][j][1] + b1);
            float2 v1 = make_float2(acc[i][j][2] + b0, acc[i][j][3] + b1);
            *reinterpret_cast<float2*>(out + (size_t)m0r * SSH + (size_t)s * HH + n0 + c) = v0;
            *reinterpret_cast<float2*>(out + (size_t)(m0r + 8) * SSH + (size_t)s * HH + n0 + c) = v1;
        }
    }
}

extern "C" void kernel_launch(void* const* d_in, const int* in_sizes, int n_in,
                              void* d_out, int out_size)
{
    const float* x    = (const float*)d_in[0];   // [128, 513, 256]
    const float* W    = (const float*)d_in[1];   // [5, 256, 256]
    const float* bias = (const float*)d_in[2];   // [5, 256]
    float* out        = (float*)d_out;           // [128, 513, 4, 64]

    cudaFuncSetAttribute(pmha_mma_kernel, cudaFuncAttributeMaxDynamicSharedMemorySize, SMTOT);
    dim3 grid(2, SSEQ);
    pmha_mma_kernel<<<grid, 256, SMTOT>>>(x, W, bias, out);
}

// round 4
// speedup vs baseline: 4.4324x; 1.3489x over previous
#include <cuda_runtime.h>
#include <cstdint>

#define SSEQ 513
#define HH   256
#define SSH  (SSEQ * HH)
#define KT   32
#define NKT  8                       // 256 / 32
#define ROWW 36                      // smem row stride in words (32 data + 4 pad)
#define ROWB 144                     // row stride bytes
#define TILEB (128 * ROWB)           // 18432 per tile
#define STAGE (2 * TILEB)            // X + W per stage = 36864
#define OBS   (2 * STAGE)            // bias sums offset = 73728
#define SMTOT (OBS + 512)            // 74240 bytes

__device__ __forceinline__ uint32_t smem_u32(const void* p) {
    uint32_t a;
    asm("{ .reg .u64 t; cvta.to.shared.u64 t, %1; cvt.u32.u64 %0, t; }" : "=r"(a) : "l"(p));
    return a;
}
__device__ __forceinline__ void cpasync16(uint32_t dst, const void* src) {
    asm volatile("cp.async.cg.shared.global [%0], [%1], 16;" :: "r"(dst), "l"(src));
}
__device__ __forceinline__ void cp_commit() {
    asm volatile("cp.async.commit_group;");
}
__device__ __forceinline__ void cp_wait1() {
    asm volatile("cp.async.wait_group 1;");
}
__device__ __forceinline__ uint32_t f2tf32(float f) {
    uint32_t r;
    asm("cvt.rna.tf32.f32 %0, %1;" : "=r"(r) : "f"(f));
    return r;
}
__device__ __forceinline__ void mma_tf32(float* d, const uint32_t* a, uint32_t b0, uint32_t b1) {
    asm volatile(
        "mma.sync.aligned.m16n8k8.row.col.f32.tf32.tf32.f32 "
        "{%0,%1,%2,%3}, {%4,%5,%6,%7}, {%8,%9}, {%0,%1,%2,%3};"
        : "+f"(d[0]), "+f"(d[1]), "+f"(d[2]), "+f"(d[3])
        : "r"(a[0]), "r"(a[1]), "r"(a[2]), "r"(a[3]), "r"(b0), "r"(b1));
}

// CTA: (n-half, s). 128 threads, 4 warps in 2x2 grid, 64x64 warp tiles.
// out[0:128, s, n0:n0+128] = x[:, s, :] @ W[idx(s)]^T + sum_l bias[l]
__global__ __launch_bounds__(128, 2)
void pmha_tf32_kernel(const float* __restrict__ x,
                      const float* __restrict__ W,
                      const float* __restrict__ bias,
                      float* __restrict__ out)
{
    extern __shared__ char smem[];
    const uint32_t sb = smem_u32(smem);
    const int tid  = threadIdx.x;
    const int lane = tid & 31;
    const int wid  = tid >> 5;
    const int tg   = lane >> 2;       // 0..7
    const int tig  = lane & 3;        // 0..3
    const int wm   = (wid >> 1) * 64; // warp m offset
    const int wn   = (wid & 1) * 64;  // warp n offset
    const int s    = blockIdx.y;
    const int n0   = blockIdx.x * 128;
    const int widx = (s < 3) ? s : ((s & 1) ? 3 : 4);

    const float* xs = x + (size_t)s * HH;
    const float* Wp = W + (size_t)widx * HH * HH + (size_t)n0 * HH;

    // prefetch helper (inline): stage kt -> buffer kt&1
    auto prefetch = [&](int kt) {
        const int k0 = kt * KT;
        const uint32_t base = sb + (kt & 1) * STAGE;
        #pragma unroll
        for (int t = 0; t < 8; ++t) {
            int id  = tid + t * 128;   // 0..1023
            int row = id >> 3;
            int c   = id & 7;
            cpasync16(base + row * ROWB + c * 16,
                      xs + (size_t)row * SSH + k0 + c * 4);
            cpasync16(base + TILEB + row * ROWB + c * 16,
                      Wp + (size_t)row * HH + k0 + c * 4);
        }
    };

    prefetch(0); cp_commit();
    prefetch(1); cp_commit();

    // bias sums for this n-half (128 threads -> 1 each)
    {
        float v = 0.0f;
        #pragma unroll
        for (int l = 0; l < 5; ++l) v += bias[l * HH + n0 + tid];
        *reinterpret_cast<float*>(smem + OBS + tid * 4) = v;
    }

    float acc[4][8][4] = {};

    for (int kt = 0; kt < NKT; ++kt) {
        cp_wait1();
        __syncthreads();

        const float* Xs = reinterpret_cast<const float*>(smem + (kt & 1) * STAGE);
        const float* Ws = Xs + TILEB / 4;

        #pragma unroll
        for (int ks = 0; ks < 4; ++ks) {
            const int ko = ks * 8;
            uint32_t a[4][4];
            uint32_t bf[8][2];
            #pragma unroll
            for (int i = 0; i < 4; ++i) {
                const float* ar0 = Xs + (wm + i * 16 + tg) * ROWW + ko;
                const float* ar1 = ar0 + 8 * ROWW;
                a[i][0] = f2tf32(ar0[tig]);
                a[i][1] = f2tf32(ar1[tig]);
                a[i][2] = f2tf32(ar0[tig + 4]);
                a[i][3] = f2tf32(ar1[tig + 4]);
            }
            #pragma unroll
            for (int j = 0; j < 8; ++j) {
                const float* br = Ws + (wn + j * 8 + tg) * ROWW + ko;
                bf[j][0] = f2tf32(br[tig]);
                bf[j][1] = f2tf32(br[tig + 4]);
            }
            #pragma unroll
            for (int i = 0; i < 4; ++i)
                #pragma unroll
                for (int j = 0; j < 8; ++j)
                    mma_tf32(acc[i][j], a[i], bf[j][0], bf[j][1]);
        }

        __syncthreads();
        if (kt + 2 < NKT) prefetch(kt + 2);
        cp_commit();
    }

    // epilogue: + bias, float2 stores
    const float* bs = reinterpret_cast<const float*>(smem + OBS);
    #pragma unroll
    for (int i = 0; i < 4; ++i) {
        const int r0 = wm + i * 16 + tg;
        float* o0 = out + (size_t)r0 * SSH + (size_t)s * HH + n0;
        float* o1 = o0 + (size_t)8 * SSH;
        #pragma unroll
        for (int j = 0; j < 8; ++j) {
            const int c = wn + j * 8 + 2 * tig;
            const float b0v = bs[c], b1v = bs[c + 1];
            float2 v0 = make_float2(acc[i][j][0] + b0v, acc[i][j][1] + b1v);
            float2 v1 = make_float2(acc[i][j][2] + b0v, acc[i][j][3] + b1v);
            *reinterpret_cast<float2*>(o0 + c) = v0;
            *reinterpret_cast<float2*>(o1 + c) = v1;
        }
    }
}

extern "C" void kernel_launch(void* const* d_in, const int* in_sizes, int n_in,
                              void* d_out, int out_size)
{
    const float* x    = (const float*)d_in[0];   // [128, 513, 256]
    const float* W    = (const float*)d_in[1];   // [5, 256, 256]
    const float* bias = (const float*)d_in[2];   // [5, 256]
    float* out        = (float*)d_out;           // [128, 513, 4, 64]

    cudaFuncSetAttribute(pmha_tf32_kernel, cudaFuncAttributeMaxDynamicSharedMemorySize, SMTOT);
    dim3 grid(2, SSEQ);
    pmha_tf32_kernel<<<grid, 128, SMTOT>>>(x, W, bias, out);
}

// round 5
// speedup vs baseline: 4.4385x; 1.0014x over previous
#include <cuda_runtime.h>
#include <cstdint>

#define SSEQ 513
#define HH   256
#define SSH  (SSEQ * HH)
#define KT   32
#define NKT  8                       // 256 / 32
#define ROWW 36                      // smem row stride in words (32 data + 4 pad)
#define ROWB 144                     // row stride bytes
#define TILEB (128 * ROWB)           // 18432 per tile
#define STAGE (2 * TILEB)            // X + W per stage = 36864
#define OBS   (2 * STAGE)            // bias sums offset = 73728
#define SMTOT (OBS + 512)            // 74240 bytes

__device__ __forceinline__ uint32_t smem_u32(const void* p) {
    uint32_t a;
    asm("{ .reg .u64 t; cvta.to.shared.u64 t, %1; cvt.u32.u64 %0, t; }" : "=r"(a) : "l"(p));
    return a;
}
__device__ __forceinline__ void cpasync16(uint32_t dst, const void* src) {
    asm volatile("cp.async.cg.shared.global [%0], [%1], 16;" :: "r"(dst), "l"(src));
}
__device__ __forceinline__ void cp_commit() {
    asm volatile("cp.async.commit_group;");
}
__device__ __forceinline__ void cp_wait1() {
    asm volatile("cp.async.wait_group 1;");
}
__device__ __forceinline__ uint32_t f2tf32(float f) {
    uint32_t r;
    asm("cvt.rna.tf32.f32 %0, %1;" : "=r"(r) : "f"(f));
    return r;
}
__device__ __forceinline__ void mma_tf32(float* d, const uint32_t* a, uint32_t b0, uint32_t b1) {
    asm volatile(
        "mma.sync.aligned.m16n8k8.row.col.f32.tf32.tf32.f32 "
        "{%0,%1,%2,%3}, {%4,%5,%6,%7}, {%8,%9}, {%0,%1,%2,%3};"
        : "+f"(d[0]), "+f"(d[1]), "+f"(d[2]), "+f"(d[3])
        : "r"(a[0]), "r"(a[1]), "r"(a[2]), "r"(a[3]), "r"(b0), "r"(b1));
}

// CTA: (n-half, s). 256 threads, 8 warps in 2x4 grid, 64x32 warp tiles.
// out[0:128, s, n0:n0+128] = x[:, s, :] @ W[idx(s)]^T + sum_l bias[l]
__global__ __launch_bounds__(256, 2)
void pmha_tf32_kernel(const float* __restrict__ x,
                      const float* __restrict__ W,
                      const float* __restrict__ bias,
                      float* __restrict__ out)
{
    extern __shared__ char smem[];
    const uint32_t sb = smem_u32(smem);
    const int tid  = threadIdx.x;
    const int lane = tid & 31;
    const int wid  = tid >> 5;
    const int tg   = lane >> 2;       // 0..7
    const int tig  = lane & 3;        // 0..3
    const int wm   = (wid >> 2) * 64; // warp m offset (0,64)
    const int wn   = (wid & 3) * 32;  // warp n offset (0,32,64,96)
    const int s    = blockIdx.y;
    const int n0   = blockIdx.x * 128;
    const int widx = (s < 3) ? s : ((s & 1) ? 3 : 4);

    const float* xs = x + (size_t)s * HH;
    const float* Wp = W + (size_t)widx * HH * HH + (size_t)n0 * HH;

    // prefetch: stage kt -> buffer kt&1 (X and W tiles, 128x32 fp32 each)
    auto prefetch = [&](int kt) {
        const int k0 = kt * KT;
        const uint32_t base = sb + (kt & 1) * STAGE;
        #pragma unroll
        for (int t = 0; t < 4; ++t) {
            int id  = tid + t * 256;   // 0..1023
            int row = id >> 3;
            int c   = id & 7;
            cpasync16(base + row * ROWB + c * 16,
                      xs + (size_t)row * SSH + k0 + c * 4);
            cpasync16(base + TILEB + row * ROWB + c * 16,
                      Wp + (size_t)row * HH + k0 + c * 4);
        }
    };

    prefetch(0); cp_commit();
    prefetch(1); cp_commit();

    // bias sums for this n-half
    if (tid < 128) {
        float v = 0.0f;
        #pragma unroll
        for (int l = 0; l < 5; ++l) v += bias[l * HH + n0 + tid];
        *reinterpret_cast<float*>(smem + OBS + tid * 4) = v;
    }

    float acc[4][4][4] = {};   // [m16 tile][n8 tile][frag]

    for (int kt = 0; kt < NKT; ++kt) {
        cp_wait1();
        __syncthreads();

        const float* Xs = reinterpret_cast<const float*>(smem + (kt & 1) * STAGE);
        const float* Ws = Xs + TILEB / 4;

        #pragma unroll
        for (int ks = 0; ks < 4; ++ks) {
            const int ko = ks * 8;
            uint32_t a[4][4];
            uint32_t bf[4][2];
            #pragma unroll
            for (int i = 0; i < 4; ++i) {
                const float* ar0 = Xs + (wm + i * 16 + tg) * ROWW + ko;
                const float* ar1 = ar0 + 8 * ROWW;
                a[i][0] = f2tf32(ar0[tig]);
                a[i][1] = f2tf32(ar1[tig]);
                a[i][2] = f2tf32(ar0[tig + 4]);
                a[i][3] = f2tf32(ar1[tig + 4]);
            }
            #pragma unroll
            for (int j = 0; j < 4; ++j) {
                const float* br = Ws + (wn + j * 8 + tg) * ROWW + ko;
                bf[j][0] = f2tf32(br[tig]);
                bf[j][1] = f2tf32(br[tig + 4]);
            }
            #pragma unroll
            for (int i = 0; i < 4; ++i)
                #pragma unroll
                for (int j = 0; j < 4; ++j)
                    mma_tf32(acc[i][j], a[i], bf[j][0], bf[j][1]);
        }

        __syncthreads();
        if (kt + 2 < NKT) prefetch(kt + 2);
        cp_commit();
    }

    // epilogue: + bias, float2 stores
    const float* bs = reinterpret_cast<const float*>(smem + OBS);
    #pragma unroll
    for (int i = 0; i < 4; ++i) {
        const int r0 = wm + i * 16 + tg;
        float* o0 = out + (size_t)r0 * SSH + (size_t)s * HH + n0;
        float* o1 = o0 + (size_t)8 * SSH;
        #pragma unroll
        for (int j = 0; j < 4; ++j) {
            const int c = wn + j * 8 + 2 * tig;
            const float b0v = bs[c], b1v = bs[c + 1];
            float2 v0 = make_float2(acc[i][j][0] + b0v, acc[i][j][1] + b1v);
            float2 v1 = make_float2(acc[i][j][2] + b0v, acc[i][j][3] + b1v);
            *reinterpret_cast<float2*>(o0 + c) = v0;
            *reinterpret_cast<float2*>(o1 + c) = v1;
        }
    }
}

extern "C" void kernel_launch(void* const* d_in, const int* in_sizes, int n_in,
                              void* d_out, int out_size)
{
    const float* x    = (const float*)d_in[0];   // [128, 513, 256]
    const float* W    = (const float*)d_in[1];   // [5, 256, 256]
    const float* bias = (const float*)d_in[2];   // [5, 256]
    float* out        = (float*)d_out;           // [128, 513, 4, 64]

    cudaFuncSetAttribute(pmha_tf32_kernel, cudaFuncAttributeMaxDynamicSharedMemorySize, SMTOT);
    dim3 grid(2, SSEQ);
    pmha_tf32_kernel<<<grid, 256, SMTOT>>>(x, W, bias, out);
}

// round 6
// speedup vs baseline: 4.8335x; 1.0890x over previous
#include <cuda_runtime.h>
#include <cuda_fp16.h>
#include <cstdint>

#define SSEQ 513
#define HH   256
#define SSH  (SSEQ * HH)
#define KT   32
#define NKT  8                        // 256 / 32
#define ROWB 80                       // 32 fp16 = 64B + 16B pad (ldmatrix conflict-free: 5 mod 8)
#define TILEB (128 * ROWB)            // 10240
#define STAGE (2 * TILEB)             // X + W per stage = 20480
#define OBS   (2 * STAGE)             // 40960
#define SMTOT (OBS + 512)             // 41472 bytes

__device__ __forceinline__ uint32_t smem_u32(const void* p) {
    uint32_t a;
    asm("{ .reg .u64 t; cvta.to.shared.u64 t, %1; cvt.u32.u64 %0, t; }" : "=r"(a) : "l"(p));
    return a;
}
__device__ __forceinline__ void ldsm_x4(uint32_t* r, uint32_t addr) {
    asm volatile("ldmatrix.sync.aligned.m8n8.x4.shared.b16 {%0,%1,%2,%3}, [%4];"
                 : "=r"(r[0]), "=r"(r[1]), "=r"(r[2]), "=r"(r[3]) : "r"(addr));
}
__device__ __forceinline__ void mma_f16(float* d, const uint32_t* a, uint32_t b0, uint32_t b1) {
    asm volatile(
        "mma.sync.aligned.m16n8k16.row.col.f32.f16.f16.f32 "
        "{%0,%1,%2,%3}, {%4,%5,%6,%7}, {%8,%9}, {%0,%1,%2,%3};"
        : "+f"(d[0]), "+f"(d[1]), "+f"(d[2]), "+f"(d[3])
        : "r"(a[0]), "r"(a[1]), "r"(a[2]), "r"(a[3]), "r"(b0), "r"(b1));
}
__device__ __forceinline__ uint2 f4_to_h4(float4 v) {
    __half2 h0 = __floats2half2_rn(v.x, v.y);
    __half2 h1 = __floats2half2_rn(v.z, v.w);
    uint2 u;
    u.x = *reinterpret_cast<uint32_t*>(&h0);
    u.y = *reinterpret_cast<uint32_t*>(&h1);
    return u;
}

// CTA: (n-half, s). 256 threads, 8 warps in 2x4 grid, 64x32 warp tiles.
// out[0:128, s, n0:n0+128] = x[:, s, :] @ W[idx(s)]^T + sum_l bias[l]
__global__ __launch_bounds__(256, 2)
void pmha_f16_kernel(const float* __restrict__ x,
                     const float* __restrict__ W,
                     const float* __restrict__ bias,
                     float* __restrict__ out)
{
    extern __shared__ char smem[];
    const uint32_t sb = smem_u32(smem);
    const int tid  = threadIdx.x;
    const int lane = tid & 31;
    const int wid  = tid >> 5;
    const int tg   = lane >> 2;
    const int tig  = lane & 3;
    const int wm   = (wid >> 2) * 64;  // warp m offset (0,64)
    const int wn   = (wid & 3) * 32;   // warp n offset (0,32,64,96)
    const int s    = blockIdx.y;
    const int n0   = blockIdx.x * 128;
    const int widx = (s < 3) ? s : ((s & 1) ? 3 : 4);

    const float* xs = x + (size_t)s * HH;
    const float* Wp = W + (size_t)widx * HH * HH + (size_t)n0 * HH;

    // bias sums for this n-half
    if (tid < 128) {
        float v = 0.0f;
        #pragma unroll
        for (int l = 0; l < 5; ++l) v += bias[l * HH + n0 + tid];
        *reinterpret_cast<float*>(smem + OBS + tid * 4) = v;
    }

    // per-thread staging addresses: 4 float4 per tile for X and W each
    const int srow = tid >> 3;         // 0..31 base row (stride 32 over 4 steps)
    const int sc4  = tid & 7;          // float4 column 0..7

    float4 rx[4], rw[4];
    auto ldg = [&](int kt) {
        const int k0 = kt * KT;
        #pragma unroll
        for (int t = 0; t < 4; ++t) {
            int row = srow + t * 32;
            rx[t] = *reinterpret_cast<const float4*>(xs + (size_t)row * SSH + k0 + sc4 * 4);
            rw[t] = *reinterpret_cast<const float4*>(Wp + (size_t)row * HH + k0 + sc4 * 4);
        }
    };
    auto sts = [&](int kt) {
        char* base = smem + (kt & 1) * STAGE;
        #pragma unroll
        for (int t = 0; t < 4; ++t) {
            int row = srow + t * 32;
            uint32_t off = (uint32_t)row * ROWB + (uint32_t)sc4 * 8;
            *reinterpret_cast<uint2*>(base + off)          = f4_to_h4(rx[t]);
            *reinterpret_cast<uint2*>(base + TILEB + off)  = f4_to_h4(rw[t]);
        }
    };

    // ldmatrix base addresses
    const int lr = lane & 15;
    const int lc = lane >> 4;
    uint32_t aA[4], aB[2];
    #pragma unroll
    for (int i = 0; i < 4; ++i)
        aA[i] = sb + (uint32_t)(wm + i * 16 + lr) * ROWB + lc * 16;
    #pragma unroll
    for (int jj = 0; jj < 2; ++jj)
        aB[jj] = sb + TILEB + (uint32_t)(wn + jj * 16 + lr) * ROWB + lc * 16;

    float acc[4][4][4] = {};

    ldg(0);
    for (int kt = 0; kt < NKT; ++kt) {
        sts(kt);
        if (kt + 1 < NKT) ldg(kt + 1);   // overlaps with compute below
        __syncthreads();

        const uint32_t bufoff = (kt & 1) * STAGE;
        #pragma unroll
        for (int ks = 0; ks < 2; ++ks) {
            const uint32_t off = bufoff + ks * 32;   // 16 fp16 = 32B per k16 step
            uint32_t a[4][4], b[2][4];
            #pragma unroll
            for (int i = 0; i < 4; ++i) ldsm_x4(a[i], aA[i] + off);
            #pragma unroll
            for (int jj = 0; jj < 2; ++jj) ldsm_x4(b[jj], aB[jj] + off);
            #pragma unroll
            for (int i = 0; i < 4; ++i)
                #pragma unroll
                for (int j = 0; j < 4; ++j) {
                    const int jj = j >> 1, sel = j & 1;
                    mma_f16(acc[i][j], a[i], b[jj][sel], b[jj][sel + 2]);
                }
        }
        // NOTE: no second barrier needed — next iteration writes the OTHER buffer,
        // whose readers all passed this iteration's __syncthreads already.
    }

    // epilogue: + bias, float2 stores
    const float* bs = reinterpret_cast<const float*>(smem + OBS);
    #pragma unroll
    for (int i = 0; i < 4; ++i) {
        const int r0 = wm + i * 16 + tg;
        float* o0 = out + (size_t)r0 * SSH + (size_t)s * HH + n0;
        float* o1 = o0 + (size_t)8 * SSH;
        #pragma unroll
        for (int j = 0; j < 4; ++j) {
            const int c = wn + j * 8 + 2 * tig;
            const float b0v = bs[c], b1v = bs[c + 1];
            float2 v0 = make_float2(acc[i][j][0] + b0v, acc[i][j][1] + b1v);
            float2 v1 = make_float2(acc[i][j][2] + b0v, acc[i][j][3] + b1v);
            *reinterpret_cast<float2*>(o0 + c) = v0;
            *reinterpret_cast<float2*>(o1 + c) = v1;
        }
    }
}

extern "C" void kernel_launch(void* const* d_in, const int* in_sizes, int n_in,
                              void* d_out, int out_size)
{
    const float* x    = (const float*)d_in[0];   // [128, 513, 256]
    const float* W    = (const float*)d_in[1];   // [5, 256, 256]
    const float* bias = (const float*)d_in[2];   // [5, 256]
    float* out        = (float*)d_out;           // [128, 513, 4, 64]

    cudaFuncSetAttribute(pmha_f16_kernel, cudaFuncAttributeMaxDynamicSharedMemorySize, SMTOT);
    dim3 grid(2, SSEQ);
    pmha_f16_kernel<<<grid, 256, SMTOT>>>(x, W, bias, out);
}

// round 7
// speedup vs baseline: 5.2226x; 1.0805x over previous
#include <cuda_runtime.h>
#include <cuda_fp16.h>
#include <cstdint>

#define BB   128
#define SSEQ 513
#define HH   256
#define SSH  (SSEQ * HH)
#define SBH  (BB * HH)               // 32768: gx row-block per s

#define NX   (BB * SSEQ * HH)        // 16,809,984
#define NX8  (NX / 8)                // 2,101,248
#define NW   (5 * HH * HH)           // 327,680
#define NW8  (NW / 8)                // 40,960
#define NCVT (NX8 + NW8 + 32)

// fp16 scratch (static device globals — allowed; no runtime allocation)
__device__ __half gx[NX];            // [s][b][h]  (transposed for contiguous GEMM tiles)
__device__ __half gw[NW];            // [widx][n][h]
__device__ float  gbsum[HH];         // sum of 5 bias vectors

// ---------------- kernel 2 tiling ----------------
#define KT    32
#define NKT   8
#define NSTG  4
#define ROWB  80                     // 32 fp16 = 64B + 16B pad (ldmatrix conflict-free)
#define TILEB (128 * ROWB)           // 10240
#define STAGE (2 * TILEB)            // 20480
#define SMTOT (NSTG * STAGE)         // 81920

__device__ __forceinline__ uint32_t smem_u32(const void* p) {
    uint32_t a;
    asm("{ .reg .u64 t; cvta.to.shared.u64 t, %1; cvt.u32.u64 %0, t; }" : "=r"(a) : "l"(p));
    return a;
}
__device__ __forceinline__ void cpasync16(uint32_t dst, const void* src) {
    asm volatile("cp.async.ca.shared.global [%0], [%1], 16;" :: "r"(dst), "l"(src));
}
__device__ __forceinline__ void cp_commit() { asm volatile("cp.async.commit_group;"); }
__device__ __forceinline__ void cp_wait2()  { asm volatile("cp.async.wait_group 2;"); }
__device__ __forceinline__ void ldsm_x4(uint32_t* r, uint32_t addr) {
    asm volatile("ldmatrix.sync.aligned.m8n8.x4.shared.b16 {%0,%1,%2,%3}, [%4];"
                 : "=r"(r[0]), "=r"(r[1]), "=r"(r[2]), "=r"(r[3]) : "r"(addr));
}
__device__ __forceinline__ void mma_f16(float* d, const uint32_t* a, uint32_t b0, uint32_t b1) {
    asm volatile(
        "mma.sync.aligned.m16n8k16.row.col.f32.f16.f16.f32 "
        "{%0,%1,%2,%3}, {%4,%5,%6,%7}, {%8,%9}, {%0,%1,%2,%3};"
        : "+f"(d[0]), "+f"(d[1]), "+f"(d[2]), "+f"(d[3])
        : "r"(a[0]), "r"(a[1]), "r"(a[2]), "r"(a[3]), "r"(b0), "r"(b1));
}
__device__ __forceinline__ uint2 f4_to_h4(float4 v) {
    __half2 h0 = __floats2half2_rn(v.x, v.y);
    __half2 h1 = __floats2half2_rn(v.z, v.w);
    uint2 u;
    u.x = *reinterpret_cast<uint32_t*>(&h0);
    u.y = *reinterpret_cast<uint32_t*>(&h1);
    return u;
}

// ---- kernel 1: fp32 -> fp16 conversion + x transpose + bias presum ----
__global__ __launch_bounds__(256)
void cvt_kernel(const float* __restrict__ x,
                const float* __restrict__ W,
                const float* __restrict__ bias)
{
    const uint32_t id = blockIdx.x * 256 + threadIdx.x;
    if (id < NX8) {
        const size_t f = (size_t)id * 8;
        const int b   = (int)(f / (SSEQ * HH));
        const int rem = (int)(f % (SSEQ * HH));
        const int s   = rem / HH;
        const int h   = rem % HH;
        float4 v0 = *reinterpret_cast<const float4*>(x + f);
        float4 v1 = *reinterpret_cast<const float4*>(x + f + 4);
        uint4 o;
        uint2 a = f4_to_h4(v0), c = f4_to_h4(v1);
        o.x = a.x; o.y = a.y; o.z = c.x; o.w = c.y;
        *reinterpret_cast<uint4*>(&gx[(size_t)s * SBH + (size_t)b * HH + h]) = o;
    } else if (id < NX8 + NW8) {
        const size_t f = (size_t)(id - NX8) * 8;
        float4 v0 = *reinterpret_cast<const float4*>(W + f);
        float4 v1 = *reinterpret_cast<const float4*>(W + f + 4);
        uint4 o;
        uint2 a = f4_to_h4(v0), c = f4_to_h4(v1);
        o.x = a.x; o.y = a.y; o.z = c.x; o.w = c.y;
        *reinterpret_cast<uint4*>(&gw[f]) = o;
    } else if (id < NCVT) {
        const int t = (int)(id - NX8 - NW8);   // 0..31, 8 outputs each
        #pragma unroll
        for (int j = 0; j < 8; ++j) {
            const int c = t * 8 + j;
            float v = 0.0f;
            #pragma unroll
            for (int l = 0; l < 5; ++l) v += bias[l * HH + c];
            gbsum[c] = v;
        }
    }
}

// ---- kernel 2: fp16 GEMM, 4-stage cp.async pipeline ----
// CTA (n-half, s): out[0:128, s, n0:n0+128] = x_s @ W[idx]^T + bsum
__global__ __launch_bounds__(256, 2)
void pmha_f16_pipe_kernel(float* __restrict__ out)
{
    extern __shared__ char smem[];
    const uint32_t sb = smem_u32(smem);
    const int tid  = threadIdx.x;
    const int lane = tid & 31;
    const int wid  = tid >> 5;
    const int tg   = lane >> 2;
    const int tig  = lane & 3;
    const int wm   = (wid >> 2) * 64;
    const int wn   = (wid & 3) * 32;
    const int s    = blockIdx.y;
    const int n0   = blockIdx.x * 128;
    const int widx = (s < 3) ? s : ((s & 1) ? 3 : 4);

    const __half* xs = gx + (size_t)s * SBH;                    // 128 rows x 256, contiguous block
    const __half* Wp = gw + (size_t)widx * (HH * HH) + (size_t)n0 * HH;

    // cp.async mapping: 512 chunks of 16B per tile per matrix; 2 per thread each
    const int prow = tid >> 2;        // 0..63 (stride 64 over 2 steps)
    const int pc   = tid & 3;         // 16B chunk 0..3

    auto prefetch = [&](int kt) {
        const int k0 = kt * KT;
        const uint32_t base = sb + (kt & (NSTG - 1)) * STAGE;
        #pragma unroll
        for (int t = 0; t < 2; ++t) {
            const int row = prow + t * 64;
            const uint32_t off = (uint32_t)row * ROWB + (uint32_t)pc * 16;
            cpasync16(base + off,         xs + (size_t)row * HH + k0 + pc * 8);
            cpasync16(base + TILEB + off, Wp + (size_t)row * HH + k0 + pc * 8);
        }
    };

    prefetch(0); cp_commit();
    prefetch(1); cp_commit();
    prefetch(2); cp_commit();

    // ldmatrix base addresses (within a stage)
    const int lr = lane & 15;
    const int lc = lane >> 4;
    uint32_t aA[4], aB[2];
    #pragma unroll
    for (int i = 0; i < 4; ++i)
        aA[i] = sb + (uint32_t)(wm + i * 16 + lr) * ROWB + lc * 16;
    #pragma unroll
    for (int jj = 0; jj < 2; ++jj)
        aB[jj] = sb + TILEB + (uint32_t)(wn + jj * 16 + lr) * ROWB + lc * 16;

    float acc[4][4][4] = {};

    for (int kt = 0; kt < NKT; ++kt) {
        cp_wait2();
        __syncthreads();

        if (kt + 3 < NKT) prefetch(kt + 3);
        cp_commit();   // always commit (possibly empty) to keep group accounting fixed

        const uint32_t stoff = (kt & (NSTG - 1)) * STAGE;
        #pragma unroll
        for (int ks = 0; ks < 2; ++ks) {
            const uint32_t off = stoff + ks * 32;
            uint32_t a[4][4], b[2][4];
            #pragma unroll
            for (int i = 0; i < 4; ++i) ldsm_x4(a[i], aA[i] + off);
            #pragma unroll
            for (int jj = 0; jj < 2; ++jj) ldsm_x4(b[jj], aB[jj] + off);
            #pragma unroll
            for (int i = 0; i < 4; ++i)
                #pragma unroll
                for (int j = 0; j < 4; ++j) {
                    const int jj = j >> 1, sel = j & 1;
                    mma_f16(acc[i][j], a[i], b[jj][sel], b[jj][sel + 2]);
                }
        }
        __syncthreads();   // all reads of this stage done before it is refilled
    }

    // epilogue: + bias (gbsum is L2-hot), float2 stores
    #pragma unroll
    for (int i = 0; i < 4; ++i) {
        const int r0 = wm + i * 16 + tg;
        float* o0 = out + (size_t)r0 * SSH + (size_t)s * HH + n0;
        float* o1 = o0 + (size_t)8 * SSH;
        #pragma unroll
        for (int j = 0; j < 4; ++j) {
            const int c = wn + j * 8 + 2 * tig;
            const float b0v = gbsum[n0 + c], b1v = gbsum[n0 + c + 1];
            float2 v0 = make_float2(acc[i][j][0] + b0v, acc[i][j][1] + b1v);
            float2 v1 = make_float2(acc[i][j][2] + b0v, acc[i][j][3] + b1v);
            *reinterpret_cast<float2*>(o0 + c) = v0;
            *reinterpret_cast<float2*>(o1 + c) = v1;
        }
    }
}

extern "C" void kernel_launch(void* const* d_in, const int* in_sizes, int n_in,
                              void* d_out, int out_size)
{
    const float* x    = (const float*)d_in[0];   // [128, 513, 256]
    const float* W    = (const float*)d_in[1];   // [5, 256, 256]
    const float* bias = (const float*)d_in[2];   // [5, 256]
    float* out        = (float*)d_out;           // [128, 513, 4, 64]

    cvt_kernel<<<(NCVT + 255) / 256, 256>>>(x, W, bias);

    cudaFuncSetAttribute(pmha_f16_pipe_kernel, cudaFuncAttributeMaxDynamicSharedMemorySize, SMTOT);
    dim3 grid(2, SSEQ);
    pmha_f16_pipe_kernel<<<grid, 256, SMTOT>>>(out);
}

// round 8
// speedup vs baseline: 5.7542x; 1.1018x over previous
#include <cuda_runtime.h>
#include <cuda_fp16.h>
#include <cstdint>

#define BB   128
#define SSEQ 513
#define HH   256
#define SSH  (SSEQ * HH)
#define SBH  (BB * HH)               // 32768: gx row-block per s

#define NX   (BB * SSEQ * HH)
#define NX8  (NX / 8)
#define NW   (5 * HH * HH)
#define NW8  (NW / 8)
#define NCVT (NX8 + NW8 + 32)

__device__ __half gx[NX];            // [s][b][h]
__device__ __half gw[NW];            // [widx][n][h]
__device__ float  gbsum[HH];

// ---------------- GEMM tiling: k=64 stages, 2-stage ring, 1 barrier/tile ----
#define KT    64
#define NKT   4                      // 256 / 64
#define NSTG  2
#define ROWB  144                    // 64 fp16 = 128B + 16B pad (stride 9*16B, ldmatrix conflict-free)
#define TILEB (128 * ROWB)           // 18432
#define STAGE (2 * TILEB)            // X + W = 36864
#define SMTOT (NSTG * STAGE)         // 73728

__device__ __forceinline__ uint32_t smem_u32(const void* p) {
    uint32_t a;
    asm("{ .reg .u64 t; cvta.to.shared.u64 t, %1; cvt.u32.u64 %0, t; }" : "=r"(a) : "l"(p));
    return a;
}
__device__ __forceinline__ void cpasync16(uint32_t dst, const void* src) {
    asm volatile("cp.async.ca.shared.global [%0], [%1], 16;" :: "r"(dst), "l"(src));
}
__device__ __forceinline__ void cp_commit() { asm volatile("cp.async.commit_group;"); }
__device__ __forceinline__ void cp_wait0()  { asm volatile("cp.async.wait_group 0;"); }
__device__ __forceinline__ void ldsm_x4(uint32_t* r, uint32_t addr) {
    asm volatile("ldmatrix.sync.aligned.m8n8.x4.shared.b16 {%0,%1,%2,%3}, [%4];"
                 : "=r"(r[0]), "=r"(r[1]), "=r"(r[2]), "=r"(r[3]) : "r"(addr));
}
__device__ __forceinline__ void mma_f16(float* d, const uint32_t* a, uint32_t b0, uint32_t b1) {
    asm volatile(
        "mma.sync.aligned.m16n8k16.row.col.f32.f16.f16.f32 "
        "{%0,%1,%2,%3}, {%4,%5,%6,%7}, {%8,%9}, {%0,%1,%2,%3};"
        : "+f"(d[0]), "+f"(d[1]), "+f"(d[2]), "+f"(d[3])
        : "r"(a[0]), "r"(a[1]), "r"(a[2]), "r"(a[3]), "r"(b0), "r"(b1));
}
__device__ __forceinline__ uint2 f4_to_h4(float4 v) {
    __half2 h0 = __floats2half2_rn(v.x, v.y);
    __half2 h1 = __floats2half2_rn(v.z, v.w);
    uint2 u;
    u.x = *reinterpret_cast<uint32_t*>(&h0);
    u.y = *reinterpret_cast<uint32_t*>(&h1);
    return u;
}

// ---- kernel 1: fp32 -> fp16 conversion + x transpose + bias presum ----
__global__ __launch_bounds__(256)
void cvt_kernel(const float* __restrict__ x,
                const float* __restrict__ W,
                const float* __restrict__ bias)
{
    const uint32_t id = blockIdx.x * 256 + threadIdx.x;
    if (id < NX8) {
        const size_t f = (size_t)id * 8;
        const int b   = (int)(f / (SSEQ * HH));
        const int rem = (int)(f % (SSEQ * HH));
        const int s   = rem / HH;
        const int h   = rem % HH;
        float4 v0 = *reinterpret_cast<const float4*>(x + f);
        float4 v1 = *reinterpret_cast<const float4*>(x + f + 4);
        uint4 o;
        uint2 a = f4_to_h4(v0), c = f4_to_h4(v1);
        o.x = a.x; o.y = a.y; o.z = c.x; o.w = c.y;
        *reinterpret_cast<uint4*>(&gx[(size_t)s * SBH + (size_t)b * HH + h]) = o;
    } else if (id < NX8 + NW8) {
        const size_t f = (size_t)(id - NX8) * 8;
        float4 v0 = *reinterpret_cast<const float4*>(W + f);
        float4 v1 = *reinterpret_cast<const float4*>(W + f + 4);
        uint4 o;
        uint2 a = f4_to_h4(v0), c = f4_to_h4(v1);
        o.x = a.x; o.y = a.y; o.z = c.x; o.w = c.y;
        *reinterpret_cast<uint4*>(&gw[f]) = o;
    } else if (id < NCVT) {
        const int t = (int)(id - NX8 - NW8);
        #pragma unroll
        for (int j = 0; j < 8; ++j) {
            const int c = t * 8 + j;
            float v = 0.0f;
            #pragma unroll
            for (int l = 0; l < 5; ++l) v += bias[l * HH + c];
            gbsum[c] = v;
        }
    }
}

// ---- kernel 2: fp16 GEMM, k=64 stages, single barrier per tile ----
// CTA (n-half, s): out[0:128, s, n0:n0+128] = x_s @ W[idx]^T + bsum
__global__ __launch_bounds__(256, 2)
void pmha_f16_k64_kernel(float* __restrict__ out)
{
    extern __shared__ char smem[];
    const uint32_t sb = smem_u32(smem);
    const int tid  = threadIdx.x;
    const int lane = tid & 31;
    const int wid  = tid >> 5;
    const int tg   = lane >> 2;
    const int tig  = lane & 3;
    const int wm   = (wid >> 2) * 64;
    const int wn   = (wid & 3) * 32;
    const int s    = blockIdx.y;
    const int n0   = blockIdx.x * 128;
    const int widx = (s < 3) ? s : ((s & 1) ? 3 : 4);

    const __half* xs = gx + (size_t)s * SBH;
    const __half* Wp = gw + (size_t)widx * (HH * HH) + (size_t)n0 * HH;

    // cp.async mapping: 128 rows x 8 chunks(16B) per tile per matrix; 4 per thread each
    const int prow = tid >> 3;        // 0..31 (x4 steps of 32)
    const int pc   = tid & 7;         // chunk 0..7

    auto prefetch = [&](int kt) {
        const int k0 = kt * KT;
        const uint32_t base = sb + (kt & 1) * STAGE;
        #pragma unroll
        for (int t = 0; t < 4; ++t) {
            const int row = prow + t * 32;
            const uint32_t off = (uint32_t)row * ROWB + (uint32_t)pc * 16;
            cpasync16(base + off,         xs + (size_t)row * HH + k0 + pc * 8);
            cpasync16(base + TILEB + off, Wp + (size_t)row * HH + k0 + pc * 8);
        }
    };

    prefetch(0); cp_commit();

    // ldmatrix base addresses (within a stage)
    const int lr = lane & 15;
    const int lc = lane >> 4;
    uint32_t aA[4], aB[2];
    #pragma unroll
    for (int i = 0; i < 4; ++i)
        aA[i] = sb + (uint32_t)(wm + i * 16 + lr) * ROWB + lc * 16;
    #pragma unroll
    for (int jj = 0; jj < 2; ++jj)
        aB[jj] = sb + TILEB + (uint32_t)(wn + jj * 16 + lr) * ROWB + lc * 16;

    float acc[4][4][4] = {};

    for (int kt = 0; kt < NKT; ++kt) {
        cp_wait0();           // stage kt fully arrived (loaded during previous iter)
        __syncthreads();      // visibility + all reads of stage kt-1 done

        if (kt + 1 < NKT) { prefetch(kt + 1); cp_commit(); }   // overlaps compute below

        const uint32_t stoff = (kt & 1) * STAGE;
        #pragma unroll
        for (int ks = 0; ks < 4; ++ks) {
            const uint32_t off = stoff + ks * 32;   // 16 fp16 = 32B per k16 step
            uint32_t a[4][4], b[2][4];
            #pragma unroll
            for (int i = 0; i < 4; ++i) ldsm_x4(a[i], aA[i] + off);
            #pragma unroll
            for (int jj = 0; jj < 2; ++jj) ldsm_x4(b[jj], aB[jj] + off);
            #pragma unroll
            for (int i = 0; i < 4; ++i)
                #pragma unroll
                for (int j = 0; j < 4; ++j) {
                    const int jj = j >> 1, sel = j & 1;
                    mma_f16(acc[i][j], a[i], b[jj][sel], b[jj][sel + 2]);
                }
        }
        // no trailing barrier: next iter's top barrier protects the ring slot
    }

    // epilogue: + bias (L2-hot), float2 stores
    #pragma unroll
    for (int i = 0; i < 4; ++i) {
        const int r0 = wm + i * 16 + tg;
        float* o0 = out + (size_t)r0 * SSH + (size_t)s * HH + n0;
        float* o1 = o0 + (size_t)8 * SSH;
        #pragma unroll
        for (int j = 0; j < 4; ++j) {
            const int c = wn + j * 8 + 2 * tig;
            const float b0v = gbsum[n0 + c], b1v = gbsum[n0 + c + 1];
            float2 v0 = make_float2(acc[i][j][0] + b0v, acc[i][j][1] + b1v);
            float2 v1 = make_float2(acc[i][j][2] + b0v, acc[i][j][3] + b1v);
            *reinterpret_cast<float2*>(o0 + c) = v0;
            *reinterpret_cast<float2*>(o1 + c) = v1;
        }
    }
}

extern "C" void kernel_launch(void* const* d_in, const int* in_sizes, int n_in,
                              void* d_out, int out_size)
{
    const float* x    = (const float*)d_in[0];   // [128, 513, 256]
    const float* W    = (const float*)d_in[1];   // [5, 256, 256]
    const float* bias = (const float*)d_in[2];   // [5, 256]
    float* out        = (float*)d_out;           // [128, 513, 4, 64]

    cvt_kernel<<<(NCVT + 255) / 256, 256>>>(x, W, bias);

    cudaFuncSetAttribute(pmha_f16_k64_kernel, cudaFuncAttributeMaxDynamicSharedMemorySize, SMTOT);
    dim3 grid(2, SSEQ);
    pmha_f16_k64_kernel<<<grid, 256, SMTOT>>>(out);
}